// round 16
// baseline (speedup 1.0000x reference)
#include <cuda_runtime.h>
#include <math.h>

#define NN   8192
#define NE   81920
#define NE2  1310720
#define HSZ  (1 << 18)
#define NBLK 148
#define NTHR 1024

typedef unsigned long long ull;

// ---------------- device scratch ----------------
__device__ float  g_gb;                      // gat_bias . linW
__device__ __align__(16) float4 g_nf4[NN];   // (fs, fd, fq, 0)
__device__ __align__(16) float4 g_ng4[NN];   // (gs, gd, gq, 0)
__device__ __align__(16) float4 g_srcv[NE];  // (e^{a_s}, e^{.2a_s}, q, 0)
__device__ __align__(16) float2 g_dstv[NE];  // (e^{a_d}, e^{.2a_d})
__device__ __align__(16) float2 g_numden[NE];
__device__ unsigned g_hkey[HSZ];
__device__ __align__(16) float2 g_hval[HSZ]; // (cnt, gate-sum)
__device__ float  g_deg[NN];
__device__ __align__(16) int    g_cnt2[NN];
__device__ int    g_offs2[NN + 1];
__device__ int    g_cur2[NN];
__device__ __align__(16) int2   g_rw[NE];    // (row, w bits) col-sorted
__device__ __align__(16) float  g_h1[NN * 128];
__device__ __align__(16) float  g_h2[NN * 128];
__device__ float  g_gsum[128];
__device__ ull    g_wp[3 * 8192];            // paired W: (W[k][j], W[k][j+64])
__device__ int          g_barc;
__device__ volatile int g_barp;

// ---------------- f32x2 helpers ----------------
__device__ __forceinline__ ull pack2(float v) {
    ull r; asm("mov.b64 %0, {%1, %1};" : "=l"(r) : "f"(v)); return r;
}
__device__ __forceinline__ ull pack2b(float lo, float hi) {
    ull r; asm("mov.b64 %0, {%1, %2};" : "=l"(r) : "f"(lo), "f"(hi)); return r;
}
__device__ __forceinline__ void fma2(ull& acc, ull a, ull b) {
    asm("fma.rn.f32x2 %0, %1, %2, %0;" : "+l"(acc) : "l"(a), "l"(b));
}
__device__ __forceinline__ float2 unpack2(ull v) {
    float2 r; asm("mov.b64 {%0, %1}, %2;" : "=f"(r.x), "=f"(r.y) : "l"(v)); return r;
}

__device__ __forceinline__ unsigned hash_key(unsigned key) {
    return ((key * 2654435761u) >> 14) & (HSZ - 1);
}
__device__ __forceinline__ int hash_find(unsigned key) {
    unsigned s = hash_key(key);
    while (true) {
        unsigned k = g_hkey[s];
        if (k == key) return (int)s;
        if (k == 0u) return -1;
        s = (s + 1) & (HSZ - 1);
    }
}

// ---- fused front kernel: zeroing + W pairing + per-block u/v (smem) + node scalars ----
__global__ void k_nscal(const float* __restrict__ embed, const float* __restrict__ gatW,
                        const float* __restrict__ att_src, const float* __restrict__ att_dst,
                        const float* __restrict__ linW, const float* __restrict__ gat_bias,
                        const float* __restrict__ W1, const float* __restrict__ W2,
                        const float* __restrict__ W3) {
    __shared__ __align__(16) float su[6][128];
    int tid = threadIdx.x;
    int gid = blockIdx.x * 256 + tid;          // 0 .. 262143 == HSZ

    // strided zeroing / setup (one element per thread; coalesced)
    g_hkey[gid] = 0u;
    g_hval[gid] = make_float2(0.f, 0.f);
    if (gid < NN)  { g_cnt2[gid] = 0; g_deg[gid] = 0.0f; }
    if (gid < 128) g_gsum[gid] = 0.0f;
    if (gid == 0)  { g_barc = 0; g_barp = 0; }
    if (gid < 3 * 8192) {
        int layer = gid >> 13, rem = gid & 8191;
        int k = rem >> 6, jj = rem & 63;
        const float* W = (layer == 0) ? W1 : ((layer == 1) ? W2 : W3);
        g_wp[gid] = pack2b(W[k * 128 + jj], W[k * 128 + jj + 64]);
    }
    if (blockIdx.x == 0 && tid < 32) {
        float gb = gat_bias[tid] * linW[tid] + gat_bias[tid + 32] * linW[tid + 32];
#pragma unroll
        for (int o = 16; o; o >>= 1) gb += __shfl_xor_sync(0xffffffffu, gb, o);
        if (tid == 0) g_gb = gb;
    }

    // per-block u/v into smem: 768 dots over 256 threads (3 each)
#pragma unroll
    for (int j = 0; j < 3; j++) {
        int d = tid + 256 * j;
        int q = d >> 7, k = d & 127;
        const float* a = (q == 0 || q == 3) ? att_src : ((q == 1 || q == 4) ? att_dst : linW);
        int rb = ((q < 3) ? k : (128 + k)) * 64;
        float s = 0.0f;
#pragma unroll 8
        for (int jj2 = 0; jj2 < 64; jj2++) s += gatW[rb + jj2] * a[jj2];
        su[q][k] = s;
    }
    __syncthreads();

    // per-node scalars: warp per node
    int n = blockIdx.x * 8 + (tid >> 5);
    int l = tid & 31;
    float4 e = *(const float4*)&embed[n * 128 + l * 4];
    float a0, a1, a2, a3, a4, a5;
    {
        float4 u;
        u = *(const float4*)&su[0][l * 4]; a0 = e.x*u.x + e.y*u.y + e.z*u.z + e.w*u.w;
        u = *(const float4*)&su[1][l * 4]; a1 = e.x*u.x + e.y*u.y + e.z*u.z + e.w*u.w;
        u = *(const float4*)&su[2][l * 4]; a2 = e.x*u.x + e.y*u.y + e.z*u.z + e.w*u.w;
        u = *(const float4*)&su[3][l * 4]; a3 = e.x*u.x + e.y*u.y + e.z*u.z + e.w*u.w;
        u = *(const float4*)&su[4][l * 4]; a4 = e.x*u.x + e.y*u.y + e.z*u.z + e.w*u.w;
        u = *(const float4*)&su[5][l * 4]; a5 = e.x*u.x + e.y*u.y + e.z*u.z + e.w*u.w;
    }
#pragma unroll
    for (int o = 16; o; o >>= 1) {
        a0 += __shfl_xor_sync(0xffffffffu, a0, o);
        a1 += __shfl_xor_sync(0xffffffffu, a1, o);
        a2 += __shfl_xor_sync(0xffffffffu, a2, o);
        a3 += __shfl_xor_sync(0xffffffffu, a3, o);
        a4 += __shfl_xor_sync(0xffffffffu, a4, o);
        a5 += __shfl_xor_sync(0xffffffffu, a5, o);
    }
    if (l == 0) {
        g_nf4[n] = make_float4(a0, a1, a2, 0.f);
        g_ng4[n] = make_float4(a3, a4, a5, 0.f);
    }
}

// per-edge exp factors + numden self-loop init + col histogram
__global__ void k_edge(const int* __restrict__ ei) {
    int e = blockIdx.x * blockDim.x + threadIdx.x;
    if (e >= NE) return;
    int r = ei[e], c = ei[NE + e];
    float4 a = g_nf4[r], b = g_ng4[c];
    float as = a.x + b.x, ad = a.y + b.y, q = a.z + b.z;
    float es  = __expf(as),        ed  = __expf(ad);
    float es2 = __expf(0.2f * as), ed2 = __expf(0.2f * ad);
    g_srcv[e] = make_float4(es, es2, q, 0.f);
    g_dstv[e] = make_float2(ed, ed2);
    float eal = (as + ad > 0.0f) ? es * ed : es2 * ed2;    // self-loop
    g_numden[e] = make_float2(eal * q, eal);
    atomicAdd(&g_cnt2[c], 1);
}

// 2 extended edges per thread (8 blocks/SM); extra block does the NN-scan
__global__ void __launch_bounds__(256, 8)
k_scatter(const int* __restrict__ ne) {
    __shared__ int ws[8], wo[8];
    if (blockIdx.x == NE2 / 512) {
        int t = threadIdx.x;
        int base = t * 32;
        int s = 0;
#pragma unroll
        for (int i = 0; i < 8; i++) {
            int4 v = *(const int4*)&g_cnt2[base + i * 4];
            s += v.x + v.y + v.z + v.w;
        }
        int x = s;
#pragma unroll
        for (int o = 1; o < 32; o <<= 1) {
            int y = __shfl_up_sync(0xffffffffu, x, o);
            if ((t & 31) >= o) x += y;
        }
        if ((t & 31) == 31) ws[t >> 5] = x;
        __syncthreads();
        if (t == 0) {
            int a = 0;
#pragma unroll
            for (int i = 0; i < 8; i++) { wo[i] = a; a += ws[i]; }
        }
        __syncthreads();
        int p = x - s + wo[t >> 5];
#pragma unroll
        for (int i = 0; i < 8; i++) {
            int4 v = *(const int4*)&g_cnt2[base + i * 4];
            int b = base + i * 4;
            g_offs2[b] = p;     g_cur2[b] = p;     p += v.x;
            g_offs2[b + 1] = p; g_cur2[b + 1] = p; p += v.y;
            g_offs2[b + 2] = p; g_cur2[b + 2] = p; p += v.z;
            g_offs2[b + 3] = p; g_cur2[b + 3] = p; p += v.w;
        }
        if (t == 255) g_offs2[NN] = p;
        return;
    }
    int base = (blockIdx.x * 256 + threadIdx.x) * 2;
    int2 s2 = *(const int2*)&ne[base];
    int2 d2 = *(const int2*)&ne[NE2 + base];
    float4 sv0 = g_srcv[s2.x];
    float4 sv1 = g_srcv[s2.y];
    float2 dv0 = g_dstv[d2.x];
    float2 dv1 = g_dstv[d2.y];
    float p0  = sv0.x * dv0.x, q0 = sv0.y * dv0.y;
    float p1  = sv1.x * dv1.x, q1 = sv1.y * dv1.y;
    float e0 = (p0 > 1.0f) ? p0 : q0;
    float e1 = (p1 > 1.0f) ? p1 : q1;
    atomicAdd(&g_numden[d2.x], make_float2(e0 * sv0.z, e0));
    atomicAdd(&g_numden[d2.y], make_float2(e1 * sv1.z, e1));
}

// ---------------- global barrier (nanosleep backoff) ----------------
__device__ __forceinline__ void gsync(int ph) {
    __syncthreads();
    if (threadIdx.x == 0) {
        __threadfence();
        int t = atomicAdd(&g_barc, 1);
        if (t == NBLK - 1) {
            g_barc = 0;
            __threadfence();
            g_barp = ph;
        } else {
            while (g_barp < ph) __nanosleep(32);
        }
    }
    __syncthreads();
}

// ---------------- persistent back kernel: gate/hash -> edgew -> 3 GCN layers ----------------
__global__ void __launch_bounds__(NTHR, 1)
k_mega(const int* __restrict__ ei, const float* __restrict__ noise,
       const float* __restrict__ tmp, const float* __restrict__ linb,
       const float* __restrict__ x, const float* __restrict__ Wc,
       float* __restrict__ out) {
    int tid = threadIdx.x, bid = blockIdx.x;
    __shared__ __align__(16) float sa[64][128];

    int pe0 = (bid * NE) / NBLK;
    int pe1 = ((bid + 1) * NE) / NBLK;
    int my_e = pe0 + tid;
    bool has_e = my_e < pe1;
    int my_r = 0, my_c = 0;
    unsigned my_slot = 0;

    // ---- phase 0: gate + hash insert (keep slot for phase 1) ----
    if (has_e) {
        float inv_tmp = 1.0f / tmp[0];
        float lb = linb[0];
        float2 nd = g_numden[my_e];
        float la = nd.x / nd.y + g_gb + lb;
        float nv = noise[my_e];
        float xv = (__logf(nv) - __logf(1.0f - nv) + la) * inv_tmp;
        float gate = 1.0f / (1.0f + __expf(-xv));
        my_r = ei[my_e]; my_c = ei[NE + my_e];
        unsigned key = (unsigned)my_r * 8192u + (unsigned)my_c + 1u;
        unsigned sl = hash_key(key);
        while (true) {
            unsigned old = atomicCAS(&g_hkey[sl], 0u, key);
            if (old == 0u || old == key) break;
            sl = (sl + 1) & (HSZ - 1);
        }
        my_slot = sl;
        atomicAdd(&g_hval[sl], make_float2(1.0f, gate));
    }
    gsync(1);

    // ---- phase 1: edge weight + degree + col-sorted scatter ----
    if (has_e) {
        float2 hv = g_hval[my_slot];
        int sr = hash_find((unsigned)my_c * 8192u + (unsigned)my_r + 1u);
        float srev = (sr >= 0) ? g_hval[sr].y : 0.0f;
        float em = hv.x * 0.5f * (hv.y + srev);
        float w = 1.0f / (1.0f + __expf(-em));
        atomicAdd(&g_deg[my_c], w);
        int pos = atomicAdd(&g_cur2[my_c], 1);
        g_rw[pos] = make_int2(my_r, __float_as_int(w));
    }
    gsync(2);

    // ---- 3 fused GCN layers: block-local aggregate -> smem -> GEMM (blocks 0..127) ----
    int ph = 3;
#pragma unroll 1
    for (int layer = 0; layer < 3; layer++) {
        const float* xh = (layer == 0) ? x : ((layer == 1) ? g_h1 : g_h2);
        if (bid < NN / 64) {
            int nb = bid * 64;
            // aggregate: warp per 2 nodes; rw prefetched one iteration ahead
            {
                int wid = tid >> 5, l = tid & 31;
#pragma unroll
                for (int mm = 0; mm < 2; mm++) {
                    int m = wid * 2 + mm;
                    int n = nb + m;
                    int e0 = g_offs2[n], e1 = g_offs2[n + 1];
                    float4 acc = make_float4(0.f, 0.f, 0.f, 0.f);
                    if (e0 < e1) {
                        int2 rw = g_rw[e0];
                        int elast = e1 - 1;
                        for (int i = e0 + 1; i <= e1; i++) {
                            int2 nxt = g_rw[(i < e1) ? i : elast];
                            float wt = __int_as_float(rw.y);
                            float4 xr = *(const float4*)&xh[rw.x * 128 + l * 4];
                            acc.x += wt * xr.x; acc.y += wt * xr.y;
                            acc.z += wt * xr.z; acc.w += wt * xr.w;
                            rw = nxt;
                        }
                    }
                    float invd = 1.0f / (g_deg[n] + 1.0f);
                    float4 xn = *(const float4*)&xh[n * 128 + l * 4];
                    float4 t;
                    t.x = (xn.x + acc.x) * invd; t.y = (xn.y + acc.y) * invd;
                    t.z = (xn.z + acc.z) * invd; t.w = (xn.w + acc.w) * invd;
                    *(float4*)&sa[m][l * 4] = t;
                }
            }
            __syncthreads();

            // GEMM: f32x2, 16 groups x 4 nodes
            int jj = tid & 63;         // column pair (jj, jj+64)
            int mh = tid >> 6;         // 4-node group (0..15)
            const ull* Wp = &g_wp[layer * 8192];
            ull acc2[4];
#pragma unroll
            for (int m = 0; m < 4; m++) acc2[m] = 0ull;
#pragma unroll 1
            for (int k0 = 0; k0 < 128; k0 += 4) {
                ull w0 = Wp[(k0 + 0) * 64 + jj];
                ull w1 = Wp[(k0 + 1) * 64 + jj];
                ull w2 = Wp[(k0 + 2) * 64 + jj];
                ull w3 = Wp[(k0 + 3) * 64 + jj];
#pragma unroll
                for (int m = 0; m < 4; m++) {
                    float4 a = *(const float4*)&sa[mh * 4 + m][k0];
                    fma2(acc2[m], pack2(a.x), w0);
                    fma2(acc2[m], pack2(a.y), w1);
                    fma2(acc2[m], pack2(a.z), w2);
                    fma2(acc2[m], pack2(a.w), w3);
                }
            }
            if (layer < 2) {
                float* o = layer ? g_h2 : g_h1;
#pragma unroll
                for (int m = 0; m < 4; m++) {
                    float2 v = unpack2(acc2[m]);
                    int node = nb + mh * 4 + m;
                    o[node * 128 + jj]      = fmaxf(v.x, 0.0f);
                    o[node * 128 + jj + 64] = fmaxf(v.y, 0.0f);
                }
            } else {
                float s0 = 0.0f, s1 = 0.0f;
#pragma unroll
                for (int m = 0; m < 4; m++) {
                    float2 v = unpack2(acc2[m]);
                    s0 += fmaxf(v.x, 0.0f);
                    s1 += fmaxf(v.y, 0.0f);
                }
                __syncthreads();
                sa[mh][jj]      = s0;
                sa[mh][jj + 64] = s1;
                __syncthreads();
                if (tid < 128) {
                    float s = 0.0f;
#pragma unroll
                    for (int g = 0; g < 16; g++) s += sa[g][tid];
                    atomicAdd(&g_gsum[tid], s);
                }
            }
        }
        gsync(ph++);
    }

    // ---- final: mean pool + classifier + softmax ----
    if (bid == 0 && tid < 32) {
        int lane = tid;
        float l0 = 0.0f, l1 = 0.0f;
        for (int j = lane; j < 128; j += 32) {
            float gv = __ldcg(&g_gsum[j]) * (1.0f / 8192.0f);
            l0 += gv * Wc[j * 2 + 0];
            l1 += gv * Wc[j * 2 + 1];
        }
#pragma unroll
        for (int o = 16; o; o >>= 1) {
            l0 += __shfl_xor_sync(0xffffffffu, l0, o);
            l1 += __shfl_xor_sync(0xffffffffu, l1, o);
        }
        if (lane == 0) {
            float mx = fmaxf(l0, l1);
            float e0 = __expf(l0 - mx), e1 = __expf(l1 - mx);
            float s = e0 + e1;
            out[0] = e0 / s;
            out[1] = e1 / s;
        }
    }
}

// ---------------- host launcher ----------------
extern "C" void kernel_launch(void* const* d_in, const int* in_sizes, int n_in,
                              void* d_out, int out_size) {
    const float* x        = (const float*)d_in[0];
    const float* embed    = (const float*)d_in[1];
    const float* noise    = (const float*)d_in[2];
    const float* tmp      = (const float*)d_in[3];
    const float* gatW     = (const float*)d_in[4];
    const float* att_src  = (const float*)d_in[5];
    const float* att_dst  = (const float*)d_in[6];
    const float* gat_bias = (const float*)d_in[7];
    const float* linW     = (const float*)d_in[8];
    const float* linb     = (const float*)d_in[9];
    const float* W1       = (const float*)d_in[10];
    const float* W2       = (const float*)d_in[11];
    const float* W3       = (const float*)d_in[12];
    const float* Wc       = (const float*)d_in[13];
    const int*   ei       = (const int*)d_in[14];
    const int*   ne       = (const int*)d_in[15];
    float* out = (float*)d_out;

    k_nscal<<<NN / 8, 256>>>(embed, gatW, att_src, att_dst, linW, gat_bias, W1, W2, W3);
    k_edge<<<NE / 256, 256>>>(ei);
    k_scatter<<<NE2 / 512 + 1, 256>>>(ne);
    k_mega<<<NBLK, NTHR>>>(ei, noise, tmp, linb, x, Wc, out);
}

// round 17
// speedup vs baseline: 2.4161x; 2.4161x over previous
#include <cuda_runtime.h>
#include <math.h>

#define NN   8192
#define NE   81920
#define NE2  1310720
#define HSZ  (1 << 18)
#define NBLK 148
#define NTHR 1024

typedef unsigned long long ull;

// ---------------- device scratch ----------------
__device__ __align__(16) float g_u[3][128];
__device__ __align__(16) float g_v[3][128];
__device__ float  g_gb;                      // gat_bias . linW
__device__ __align__(16) float4 g_nf4[NN];   // (fs, fd, fq, 0)
__device__ __align__(16) float4 g_ng4[NN];   // (gs, gd, gq, 0)
__device__ __align__(16) float4 g_srcv[NE];  // (e^{a_s}, e^{.2a_s}, q, 0)
__device__ __align__(16) float2 g_dstv[NE];  // (e^{a_d}, e^{.2a_d})
__device__ __align__(16) float2 g_numden[NE];
__device__ unsigned g_hkey[HSZ];
__device__ __align__(16) float2 g_hval[HSZ]; // (cnt, gate-sum)
__device__ float  g_deg[NN];
__device__ __align__(16) int    g_cnt2[NN];
__device__ int    g_offs2[NN + 1];
__device__ int    g_cur2[NN];
__device__ __align__(16) int2   g_rw[NE];    // (row, w bits) col-sorted
__device__ __align__(16) float  g_h1[NN * 128];
__device__ __align__(16) float  g_h2[NN * 128];
__device__ float  g_gsum[128];
__device__ ull    g_wp[3 * 8192];            // paired W: (W[k][j], W[k][j+64])
__device__ int          g_barc;
__device__ volatile int g_barp;

// ---------------- f32x2 helpers ----------------
__device__ __forceinline__ ull pack2(float v) {
    ull r; asm("mov.b64 %0, {%1, %1};" : "=l"(r) : "f"(v)); return r;
}
__device__ __forceinline__ ull pack2b(float lo, float hi) {
    ull r; asm("mov.b64 %0, {%1, %2};" : "=l"(r) : "f"(lo), "f"(hi)); return r;
}
__device__ __forceinline__ void fma2(ull& acc, ull a, ull b) {
    asm("fma.rn.f32x2 %0, %1, %2, %0;" : "+l"(acc) : "l"(a), "l"(b));
}
__device__ __forceinline__ float2 unpack2(ull v) {
    float2 r; asm("mov.b64 {%0, %1}, %2;" : "=f"(r.x), "=f"(r.y) : "l"(v)); return r;
}

__device__ __forceinline__ unsigned hash_key(unsigned key) {
    return ((key * 2654435761u) >> 14) & (HSZ - 1);
}
__device__ __forceinline__ int hash_find(unsigned key) {
    unsigned s = hash_key(key);
    while (true) {
        unsigned k = g_hkey[s];
        if (k == key) return (int)s;
        if (k == 0u) return -1;
        s = (s + 1) & (HSZ - 1);
    }
}

// ---------------- init: zero + uv + gb + W pairing + barrier reset ----------------
__global__ void k_init(const float* __restrict__ gatW, const float* __restrict__ att_src,
                       const float* __restrict__ att_dst, const float* __restrict__ linW,
                       const float* __restrict__ gat_bias,
                       const float* __restrict__ W1, const float* __restrict__ W2,
                       const float* __restrict__ W3) {
    int i = blockIdx.x * blockDim.x + threadIdx.x;
    if (i < HSZ) { g_hkey[i] = 0u; g_hval[i] = make_float2(0.f, 0.f); }
    if (i < NN)  { g_cnt2[i] = 0; g_deg[i] = 0.0f; }
    if (i < 128) g_gsum[i] = 0.0f;
    if (i == 0)  { g_barc = 0; g_barp = 0; }
    if (i < 768) {
        int q = i >> 7, k = i & 127;
        const float* a = (q == 0 || q == 3) ? att_src : ((q == 1 || q == 4) ? att_dst : linW);
        int rb = ((q < 3) ? k : (128 + k)) * 64;
        float s = 0.0f;
#pragma unroll 8
        for (int j = 0; j < 64; j++) s += gatW[rb + j] * a[j];
        if (q < 3) g_u[q][k] = s; else g_v[q - 3][k] = s;
    }
    if (i < 32) {
        float gb = gat_bias[i] * linW[i] + gat_bias[i + 32] * linW[i + 32];
#pragma unroll
        for (int o = 16; o; o >>= 1) gb += __shfl_xor_sync(0xffffffffu, gb, o);
        if (i == 0) g_gb = gb;
    }
    if (i < 3 * 8192) {
        int layer = i >> 13, rem = i & 8191;
        int k = rem >> 6, jj = rem & 63;
        const float* W = (layer == 0) ? W1 : ((layer == 1) ? W2 : W3);
        g_wp[i] = pack2b(W[k * 128 + jj], W[k * 128 + jj + 64]);
    }
}

// per-node scalars: 6 dots of embed row with u/v vectors; warp per node
__global__ void k_nscal(const float* __restrict__ embed) {
    int n = blockIdx.x * 8 + (threadIdx.x >> 5);
    int l = threadIdx.x & 31;
    float4 e = *(const float4*)&embed[n * 128 + l * 4];
    float a0, a1, a2, a3, a4, a5;
    {
        float4 u;
        u = *(const float4*)&g_u[0][l * 4]; a0 = e.x*u.x + e.y*u.y + e.z*u.z + e.w*u.w;
        u = *(const float4*)&g_u[1][l * 4]; a1 = e.x*u.x + e.y*u.y + e.z*u.z + e.w*u.w;
        u = *(const float4*)&g_u[2][l * 4]; a2 = e.x*u.x + e.y*u.y + e.z*u.z + e.w*u.w;
        u = *(const float4*)&g_v[0][l * 4]; a3 = e.x*u.x + e.y*u.y + e.z*u.z + e.w*u.w;
        u = *(const float4*)&g_v[1][l * 4]; a4 = e.x*u.x + e.y*u.y + e.z*u.z + e.w*u.w;
        u = *(const float4*)&g_v[2][l * 4]; a5 = e.x*u.x + e.y*u.y + e.z*u.z + e.w*u.w;
    }
#pragma unroll
    for (int o = 16; o; o >>= 1) {
        a0 += __shfl_xor_sync(0xffffffffu, a0, o);
        a1 += __shfl_xor_sync(0xffffffffu, a1, o);
        a2 += __shfl_xor_sync(0xffffffffu, a2, o);
        a3 += __shfl_xor_sync(0xffffffffu, a3, o);
        a4 += __shfl_xor_sync(0xffffffffu, a4, o);
        a5 += __shfl_xor_sync(0xffffffffu, a5, o);
    }
    if (l == 0) {
        g_nf4[n] = make_float4(a0, a1, a2, 0.f);
        g_ng4[n] = make_float4(a3, a4, a5, 0.f);
    }
}

// per-edge exp factors + numden self-loop init + col histogram
__global__ void k_edge(const int* __restrict__ ei) {
    int e = blockIdx.x * blockDim.x + threadIdx.x;
    if (e >= NE) return;
    int r = ei[e], c = ei[NE + e];
    float4 a = g_nf4[r], b = g_ng4[c];
    float as = a.x + b.x, ad = a.y + b.y, q = a.z + b.z;
    float es  = __expf(as),        ed  = __expf(ad);
    float es2 = __expf(0.2f * as), ed2 = __expf(0.2f * ad);
    g_srcv[e] = make_float4(es, es2, q, 0.f);
    g_dstv[e] = make_float2(ed, ed2);
    float eal = (as + ad > 0.0f) ? es * ed : es2 * ed2;    // self-loop
    g_numden[e] = make_float2(eal * q, eal);
    atomicAdd(&g_cnt2[c], 1);
}

// 2 extended edges per thread (max TLP, 8 blocks/SM); extra block does the NN-scan
__global__ void __launch_bounds__(256, 8)
k_scatter(const int* __restrict__ ne) {
    __shared__ int ws[8], wo[8];
    if (blockIdx.x == NE2 / 512) {
        // ---- scan of g_cnt2[8192] with 256 threads ----
        int t = threadIdx.x;
        int base = t * 32;
        int s = 0;
#pragma unroll
        for (int i = 0; i < 8; i++) {
            int4 v = *(const int4*)&g_cnt2[base + i * 4];
            s += v.x + v.y + v.z + v.w;
        }
        int x = s;
#pragma unroll
        for (int o = 1; o < 32; o <<= 1) {
            int y = __shfl_up_sync(0xffffffffu, x, o);
            if ((t & 31) >= o) x += y;
        }
        if ((t & 31) == 31) ws[t >> 5] = x;
        __syncthreads();
        if (t == 0) {
            int a = 0;
#pragma unroll
            for (int i = 0; i < 8; i++) { wo[i] = a; a += ws[i]; }
        }
        __syncthreads();
        int p = x - s + wo[t >> 5];
#pragma unroll
        for (int i = 0; i < 8; i++) {
            int4 v = *(const int4*)&g_cnt2[base + i * 4];
            int b = base + i * 4;
            g_offs2[b] = p;     g_cur2[b] = p;     p += v.x;
            g_offs2[b + 1] = p; g_cur2[b + 1] = p; p += v.y;
            g_offs2[b + 2] = p; g_cur2[b + 2] = p; p += v.z;
            g_offs2[b + 3] = p; g_cur2[b + 3] = p; p += v.w;
        }
        if (t == 255) g_offs2[NN] = p;
        return;
    }
    int base = (blockIdx.x * 256 + threadIdx.x) * 2;
    int2 s2 = *(const int2*)&ne[base];
    int2 d2 = *(const int2*)&ne[NE2 + base];
    float4 sv0 = g_srcv[s2.x];
    float4 sv1 = g_srcv[s2.y];
    float2 dv0 = g_dstv[d2.x];
    float2 dv1 = g_dstv[d2.y];
    float p0  = sv0.x * dv0.x, q0 = sv0.y * dv0.y;
    float p1  = sv1.x * dv1.x, q1 = sv1.y * dv1.y;
    float e0 = (p0 > 1.0f) ? p0 : q0;
    float e1 = (p1 > 1.0f) ? p1 : q1;
    atomicAdd(&g_numden[d2.x], make_float2(e0 * sv0.z, e0));
    atomicAdd(&g_numden[d2.y], make_float2(e1 * sv1.z, e1));
}

// ---------------- global barrier (nanosleep backoff) ----------------
__device__ __forceinline__ void gsync(int ph) {
    __syncthreads();
    if (threadIdx.x == 0) {
        __threadfence();
        int t = atomicAdd(&g_barc, 1);
        if (t == NBLK - 1) {
            g_barc = 0;
            __threadfence();
            g_barp = ph;
        } else {
            while (g_barp < ph) __nanosleep(32);
        }
    }
    __syncthreads();
}

// ---------------- persistent back kernel: gate/hash -> edgew -> 3 GCN layers ----------------
__global__ void __launch_bounds__(NTHR, 1)
k_mega(const int* __restrict__ ei, const float* __restrict__ noise,
       const float* __restrict__ tmp, const float* __restrict__ linb,
       const float* __restrict__ x, const float* __restrict__ Wc,
       float* __restrict__ out) {
    int tid = threadIdx.x, bid = blockIdx.x;
    __shared__ __align__(16) float sa[64][128];

    // balanced edge range for phases 0/1 (~554 edges per block, all SMs active)
    int pe0 = (bid * NE) / NBLK;
    int pe1 = ((bid + 1) * NE) / NBLK;
    int my_e = pe0 + tid;
    bool has_e = my_e < pe1;
    int my_r = 0, my_c = 0;
    unsigned my_slot = 0;

    // ---- phase 0: gate + hash insert (keep slot for phase 1) ----
    if (has_e) {
        float inv_tmp = 1.0f / tmp[0];
        float lb = linb[0];
        float2 nd = g_numden[my_e];
        float la = nd.x / nd.y + g_gb + lb;
        float nv = noise[my_e];
        float xv = (__logf(nv) - __logf(1.0f - nv) + la) * inv_tmp;
        float gate = 1.0f / (1.0f + __expf(-xv));
        my_r = ei[my_e]; my_c = ei[NE + my_e];
        unsigned key = (unsigned)my_r * 8192u + (unsigned)my_c + 1u;
        unsigned sl = hash_key(key);
        while (true) {
            unsigned old = atomicCAS(&g_hkey[sl], 0u, key);
            if (old == 0u || old == key) break;
            sl = (sl + 1) & (HSZ - 1);
        }
        my_slot = sl;
        atomicAdd(&g_hval[sl], make_float2(1.0f, gate));
    }
    gsync(1);

    // ---- phase 1: edge weight + degree + col-sorted scatter ----
    if (has_e) {
        float2 hv = g_hval[my_slot];
        int sr = hash_find((unsigned)my_c * 8192u + (unsigned)my_r + 1u);
        float srev = (sr >= 0) ? g_hval[sr].y : 0.0f;
        float em = hv.x * 0.5f * (hv.y + srev);
        float w = 1.0f / (1.0f + __expf(-em));
        atomicAdd(&g_deg[my_c], w);
        int pos = atomicAdd(&g_cur2[my_c], 1);
        g_rw[pos] = make_int2(my_r, __float_as_int(w));
    }
    gsync(2);

    // ---- 3 fused GCN layers: block-local aggregate -> smem -> GEMM (blocks 0..127) ----
    int ph = 3;
#pragma unroll 1
    for (int layer = 0; layer < 3; layer++) {
        const float* xh = (layer == 0) ? x : ((layer == 1) ? g_h1 : g_h2);
        if (bid < NN / 64) {
            int nb = bid * 64;
            // aggregate the block's own 64 nodes: warp per 2 nodes -> smem
            // rw prefetched one iteration ahead to break the two-load chain
            {
                int wid = tid >> 5, l = tid & 31;
#pragma unroll
                for (int mm = 0; mm < 2; mm++) {
                    int m = wid * 2 + mm;
                    int n = nb + m;
                    int e0 = g_offs2[n], e1 = g_offs2[n + 1];
                    float4 acc = make_float4(0.f, 0.f, 0.f, 0.f);
                    if (e0 < e1) {
                        int2 rw = g_rw[e0];
                        int elast = e1 - 1;
                        for (int i = e0 + 1; i <= e1; i++) {
                            int2 nxt = g_rw[(i < e1) ? i : elast];
                            float wt = __int_as_float(rw.y);
                            float4 xr = *(const float4*)&xh[rw.x * 128 + l * 4];
                            acc.x += wt * xr.x; acc.y += wt * xr.y;
                            acc.z += wt * xr.z; acc.w += wt * xr.w;
                            rw = nxt;
                        }
                    }
                    float invd = 1.0f / (g_deg[n] + 1.0f);
                    float4 xn = *(const float4*)&xh[n * 128 + l * 4];
                    float4 t;
                    t.x = (xn.x + acc.x) * invd; t.y = (xn.y + acc.y) * invd;
                    t.z = (xn.z + acc.z) * invd; t.w = (xn.w + acc.w) * invd;
                    *(float4*)&sa[m][l * 4] = t;
                }
            }
            __syncthreads();

            // GEMM: f32x2, 16 groups x 4 nodes
            int jj = tid & 63;         // column pair (jj, jj+64)
            int mh = tid >> 6;         // 4-node group (0..15)
            const ull* Wp = &g_wp[layer * 8192];
            ull acc2[4];
#pragma unroll
            for (int m = 0; m < 4; m++) acc2[m] = 0ull;
#pragma unroll 1
            for (int k0 = 0; k0 < 128; k0 += 4) {
                ull w0 = Wp[(k0 + 0) * 64 + jj];
                ull w1 = Wp[(k0 + 1) * 64 + jj];
                ull w2 = Wp[(k0 + 2) * 64 + jj];
                ull w3 = Wp[(k0 + 3) * 64 + jj];
#pragma unroll
                for (int m = 0; m < 4; m++) {
                    float4 a = *(const float4*)&sa[mh * 4 + m][k0];
                    fma2(acc2[m], pack2(a.x), w0);
                    fma2(acc2[m], pack2(a.y), w1);
                    fma2(acc2[m], pack2(a.z), w2);
                    fma2(acc2[m], pack2(a.w), w3);
                }
            }
            if (layer < 2) {
                float* o = layer ? g_h2 : g_h1;
#pragma unroll
                for (int m = 0; m < 4; m++) {
                    float2 v = unpack2(acc2[m]);
                    int node = nb + mh * 4 + m;
                    o[node * 128 + jj]      = fmaxf(v.x, 0.0f);
                    o[node * 128 + jj + 64] = fmaxf(v.y, 0.0f);
                }
            } else {
                float s0 = 0.0f, s1 = 0.0f;
#pragma unroll
                for (int m = 0; m < 4; m++) {
                    float2 v = unpack2(acc2[m]);
                    s0 += fmaxf(v.x, 0.0f);
                    s1 += fmaxf(v.y, 0.0f);
                }
                __syncthreads();
                sa[mh][jj]      = s0;
                sa[mh][jj + 64] = s1;
                __syncthreads();
                if (tid < 128) {
                    float s = 0.0f;
#pragma unroll
                    for (int g = 0; g < 16; g++) s += sa[g][tid];
                    atomicAdd(&g_gsum[tid], s);
                }
            }
        }
        gsync(ph++);
    }

    // ---- final: mean pool + classifier + softmax ----
    if (bid == 0 && tid < 32) {
        int lane = tid;
        float l0 = 0.0f, l1 = 0.0f;
        for (int j = lane; j < 128; j += 32) {
            float gv = __ldcg(&g_gsum[j]) * (1.0f / 8192.0f);
            l0 += gv * Wc[j * 2 + 0];
            l1 += gv * Wc[j * 2 + 1];
        }
#pragma unroll
        for (int o = 16; o; o >>= 1) {
            l0 += __shfl_xor_sync(0xffffffffu, l0, o);
            l1 += __shfl_xor_sync(0xffffffffu, l1, o);
        }
        if (lane == 0) {
            float mx = fmaxf(l0, l1);
            float e0 = __expf(l0 - mx), e1 = __expf(l1 - mx);
            float s = e0 + e1;
            out[0] = e0 / s;
            out[1] = e1 / s;
        }
    }
}

// ---------------- host launcher ----------------
extern "C" void kernel_launch(void* const* d_in, const int* in_sizes, int n_in,
                              void* d_out, int out_size) {
    const float* x        = (const float*)d_in[0];
    const float* embed    = (const float*)d_in[1];
    const float* noise    = (const float*)d_in[2];
    const float* tmp      = (const float*)d_in[3];
    const float* gatW     = (const float*)d_in[4];
    const float* att_src  = (const float*)d_in[5];
    const float* att_dst  = (const float*)d_in[6];
    const float* gat_bias = (const float*)d_in[7];
    const float* linW     = (const float*)d_in[8];
    const float* linb     = (const float*)d_in[9];
    const float* W1       = (const float*)d_in[10];
    const float* W2       = (const float*)d_in[11];
    const float* W3       = (const float*)d_in[12];
    const float* Wc       = (const float*)d_in[13];
    const int*   ei       = (const int*)d_in[14];
    const int*   ne       = (const int*)d_in[15];
    float* out = (float*)d_out;

    k_init<<<HSZ / 256, 256>>>(gatW, att_src, att_dst, linW, gat_bias, W1, W2, W3);
    k_nscal<<<NN / 8, 256>>>(embed);
    k_edge<<<NE / 256, 256>>>(ei);
    k_scatter<<<NE2 / 512 + 1, 256>>>(ne);
    k_mega<<<NBLK, NTHR>>>(ei, noise, tmp, linb, x, Wc, out);
}